// round 6
// baseline (speedup 1.0000x reference)
#include <cuda_runtime.h>

#define BSZ 4
#define SEQ 256
#define DIM 128
#define HID 128
#define DFF 512
#define MROWS (BSZ*SEQ)   // 1024
#define LGSZ (BSZ*SEQ*SEQ)

// ---------------- scratch (device globals; no allocations) ----------------
__device__ float g_Wbig1[DIM*384];
__device__ float g_Wbig2[DIM*384];
__device__ float g_bbig1[384];
__device__ float g_bbig2[384];
__device__ float g_buf1[MROWS*384];   // [v1 | T1A | T1B]
__device__ float g_buf2[MROWS*384];   // [pk | TkA | TkB]
__device__ float g_Tq  [MROWS*256];   // [TqA | TqB]
__device__ float g_vw  [2*MROWS*DIM]; // [V1@Wd1 ; V2@Wd2]
__device__ float g_lg  [4*LGSZ];      // sim partials (4 H-quarters)
__device__ float g_probs[LGSZ];
__device__ float g_o1 [MROWS*DIM];
__device__ float g_o2 [MROWS*DIM];
__device__ float g_fh [MROWS*DFF];

// ---------------- prep: biases  bbig = [bw | bw@[W1q|W1k] + [b1|0]] --------
// grid (32, 2), 256 thr. Warp per matmul column; block x==0 also copies bw.
__global__ void prep_bias_kernel(const float* __restrict__ bw1, const float* __restrict__ bw2,
                                 const float* __restrict__ W1q, const float* __restrict__ W1k,
                                 const float* __restrict__ b1,
                                 float* __restrict__ bbig1, float* __restrict__ bbig2)
{
    const float* bw = blockIdx.y ? bw2 : bw1;
    float* outp = blockIdx.y ? bbig2 : bbig1;
    int tid = threadIdx.x;
    if (blockIdx.x == 0 && tid < 128) outp[tid] = bw[tid];
    int np = blockIdx.x * 8 + (tid >> 5);   // 0..255
    int lane = tid & 31;
    const float* Wsrc = (np < 128) ? W1q : W1k;
    int col = np & 127;
    float s = 0.f;
    #pragma unroll
    for (int i = 0; i < 4; i++) {
        int k = lane + 32 * i;
        s += bw[k] * Wsrc[k * 128 + col];
    }
    #pragma unroll
    for (int o = 16; o; o >>= 1) s += __shfl_xor_sync(0xffffffffu, s, o);
    if (lane == 0) {
        if (np < 128) s += b1[col];
        outp[128 + np] = s;
    }
}

// ---------------- prep: Wbig = [Ww | Ww@W1q | Ww@W1k]  (128x384) -----------
__global__ void prep_wbig_kernel(const float* __restrict__ Ww1, const float* __restrict__ Ww2,
                                 const float* __restrict__ W1q, const float* __restrict__ W1k,
                                 float* __restrict__ Wbig1, float* __restrict__ Wbig2)
{
    const float* Ww = blockIdx.z ? Ww2 : Ww1;
    float* Wbig = blockIdx.z ? Wbig2 : Wbig1;
    int bx = blockIdx.x, m0 = blockIdx.y * 32;
    int tid = threadIdx.x;
    if (bx < 4) {                        // copy Ww into cols [0,128)
        int n0 = bx * 32;
        for (int idx = tid; idx < 1024; idx += 256) {
            int mm = idx >> 5, nn = idx & 31;
            Wbig[(m0 + mm) * 384 + n0 + nn] = Ww[(m0 + mm) * 128 + n0 + nn];
        }
        return;
    }
    int n0p = (bx - 4) * 32;
    const float* Bsrc = (n0p < 128) ? (W1q + n0p) : (W1k + n0p - 128);
    __shared__ float As[32][34], Bs[32][34];
    int tx = tid & 15, ty = tid >> 4;
    float a00 = 0.f, a01 = 0.f, a10 = 0.f, a11 = 0.f;
    for (int k0 = 0; k0 < 128; k0 += 32) {
        #pragma unroll
        for (int i = 0; i < 4; i++) {
            int idx = tid + i * 256;
            int ka = idx & 31, ma = idx >> 5;
            As[ka][ma] = Ww[(m0 + ma) * 128 + k0 + ka];
            int nb = idx & 31, kb = idx >> 5;
            Bs[kb][nb] = Bsrc[(k0 + kb) * 128 + nb];
        }
        __syncthreads();
        #pragma unroll
        for (int kk = 0; kk < 32; kk++) {
            float2 a = *(const float2*)&As[kk][ty * 2];
            float2 b = *(const float2*)&Bs[kk][tx * 2];
            a00 += a.x * b.x; a01 += a.x * b.y;
            a10 += a.y * b.x; a11 += a.y * b.y;
        }
        __syncthreads();
    }
    int m = m0 + ty * 2, n = 128 + n0p + tx * 2;
    Wbig[m * 384 + n]           = a00;
    Wbig[m * 384 + n + 1]       = a01;
    Wbig[(m + 1) * 384 + n]     = a10;
    Wbig[(m + 1) * 384 + n + 1] = a11;
}

// ---------------- batched VW = V @ Wd  (z = set*4 + b) ---------------------
// set 0: V = buf1 cols[0:128) (stride 384) @ Wd1 -> vw[0]
// set 1: V = buf2 cols[0:128) (stride 384) @ Wd2 -> vw[1]
__global__ void vw_kernel(const float* __restrict__ buf1, const float* __restrict__ buf2,
                          const float* __restrict__ Wd1, const float* __restrict__ Wd2,
                          float* __restrict__ vw)
{
    __shared__ float As[32][34];
    __shared__ float Bs[32][34];
    int z = blockIdx.z;
    int set = z >> 2, b = z & 3;
    const float* A = (set ? buf2 : buf1) + (long)b * SEQ * 384;
    const float* B = set ? Wd2 : Wd1;
    float* C = vw + (long)set * MROWS * DIM + (long)b * SEQ * DIM;
    int m0 = blockIdx.y * 32, n0 = blockIdx.x * 32;
    int tid = threadIdx.x;
    int tx = tid & 15, ty = tid >> 4;
    float a00 = 0.f, a01 = 0.f, a10 = 0.f, a11 = 0.f;

    for (int k0 = 0; k0 < 128; k0 += 32) {
        #pragma unroll
        for (int i = 0; i < 4; i++) {
            int idx = tid + i * 256;
            int ka = idx & 31, ma = idx >> 5;
            As[ka][ma] = A[(long)(m0 + ma) * 384 + k0 + ka];
            int nb = idx & 31, kb = idx >> 5;
            Bs[kb][nb] = B[(long)(k0 + kb) * 128 + n0 + nb];
        }
        __syncthreads();
        #pragma unroll
        for (int kk = 0; kk < 32; kk++) {
            float2 a = *(const float2*)&As[kk][ty * 2];
            float2 b2v = *(const float2*)&Bs[kk][tx * 2];
            a00 += a.x * b2v.x; a01 += a.x * b2v.y;
            a10 += a.y * b2v.x; a11 += a.y * b2v.y;
        }
        __syncthreads();
    }
    int m = m0 + ty * 2, n = n0 + tx * 2;
    C[(long)m * DIM + n]           = a00;
    C[(long)m * DIM + n + 1]       = a01;
    C[(long)(m + 1) * DIM + n]     = a10;
    C[(long)(m + 1) * DIM + n + 1] = a11;
}

// ---------------- SGEMM 32x64 tile, 256 thr, 2x4 micro ---------------------
__global__ void sgemm2x4_kernel(const float* __restrict__ A0, const float* __restrict__ B0,
                                const float* __restrict__ bias0, float* __restrict__ C0,
                                const float* __restrict__ A1, const float* __restrict__ B1,
                                const float* __restrict__ bias1, float* __restrict__ C1,
                                int K, int lda, int ldb, int ldc, int relu)
{
    __shared__ float As[32][34];
    __shared__ float Bs[32][68];
    int z = blockIdx.z;
    bool use1 = (z == 1) && (C1 != 0);
    const float* A = use1 ? A1 : A0;
    const float* B = use1 ? B1 : B0;
    const float* bias = use1 ? bias1 : bias0;
    float* C = use1 ? C1 : C0;
    int m0 = blockIdx.y * 32, n0 = blockIdx.x * 64;
    int tid = threadIdx.x;
    int tx = tid & 15, ty = tid >> 4;
    float acc[2][4] = {};

    for (int k0 = 0; k0 < K; k0 += 32) {
        #pragma unroll
        for (int i = 0; i < 4; i++) {          // A: 32m x 32k
            int idx = tid + i * 256;
            int ka = idx & 31, ma = idx >> 5;
            As[ka][ma] = A[(long)(m0 + ma) * lda + k0 + ka];
        }
        #pragma unroll
        for (int i = 0; i < 8; i++) {          // B: 32k x 64n
            int idx = tid + i * 256;
            int nb = idx & 63, kb = idx >> 6;
            Bs[kb][nb] = B[(long)(k0 + kb) * ldb + n0 + nb];
        }
        __syncthreads();
        #pragma unroll
        for (int kk = 0; kk < 32; kk++) {
            float2 a = *(const float2*)&As[kk][ty * 2];
            float4 b = *(const float4*)&Bs[kk][tx * 4];
            float bv[4] = {b.x, b.y, b.z, b.w};
            #pragma unroll
            for (int j = 0; j < 4; j++) {
                acc[0][j] += a.x * bv[j];
                acc[1][j] += a.y * bv[j];
            }
        }
        __syncthreads();
    }
    int m = m0 + ty * 2, n = n0 + tx * 4;
    float bb[4] = {0.f, 0.f, 0.f, 0.f};
    if (bias) {
        #pragma unroll
        for (int j = 0; j < 4; j++) bb[j] = bias[n + j];
    }
    #pragma unroll
    for (int i = 0; i < 2; i++) {
        float4 o4;
        float v0 = acc[i][0] + bb[0], v1 = acc[i][1] + bb[1];
        float v2 = acc[i][2] + bb[2], v3 = acc[i][3] + bb[3];
        if (relu) { v0=fmaxf(v0,0.f); v1=fmaxf(v1,0.f); v2=fmaxf(v2,0.f); v3=fmaxf(v3,0.f); }
        o4.x=v0; o4.y=v1; o4.z=v2; o4.w=v3;
        *(float4*)&C[(long)(m + i) * ldc + n] = o4;
    }
}

// ---------------- pairwise similarity (R3/R5-proven) -----------------------
__global__ void sim_kernel(const float* __restrict__ qbase, int ldq,
                           const float* __restrict__ kbase, int ldk,
                           const float* __restrict__ W2,
                           float* __restrict__ lg, int dual)
{
    __shared__ float sqa[32][34];
    __shared__ float sqb[32][34];
    __shared__ float skb[32][68];
    __shared__ float ska[32][68];
    __shared__ float sw[32];

    int z = blockIdx.z, b = z >> 2, hq = z & 3;
    int h0 = hq * 32;
    int q0 = blockIdx.y * 32, k0 = blockIdx.x * 64;
    const float* qp = qbase + (long)(b * SEQ + q0) * ldq;
    const float* kp = kbase + (long)(b * SEQ + k0) * ldk;
    int tid = threadIdx.x;
    int tx = tid & 15, ty = tid >> 4;
    float acc[2][4] = {};

    #pragma unroll
    for (int i = 0; i < 4; i++) {
        int idx = tid + i * 256;
        int r = idx >> 5, h = idx & 31;
        sqa[h][r] = qp[(long)r * ldq + h0 + h];
        if (dual) sqb[h][r] = qp[(long)r * ldq + 128 + h0 + h];
    }
    #pragma unroll
    for (int i = 0; i < 8; i++) {
        int idx = tid + i * 256;
        int r = idx >> 5, h = idx & 31;
        skb[h][r] = kp[(long)r * ldk + 128 + h0 + h];
        if (dual) ska[h][r] = kp[(long)r * ldk + h0 + h];
    }
    if (tid < 32) sw[tid] = W2[h0 + tid];
    __syncthreads();

    #pragma unroll 4
    for (int h = 0; h < 32; h++) {
        float w = sw[h];
        float2 a1r = *(const float2*)&sqa[h][ty * 2];
        float4 b1r = *(const float4*)&skb[h][tx * 4];
        float a1v[2] = {a1r.x, a1r.y};
        float b1v[4] = {b1r.x, b1r.y, b1r.z, b1r.w};
        #pragma unroll
        for (int i = 0; i < 2; i++)
            #pragma unroll
            for (int j = 0; j < 4; j++)
                acc[i][j] += fmaxf(a1v[i] + b1v[j], 0.f) * w;
        if (dual) {
            float2 qb = *(const float2*)&sqb[h][ty * 2];
            float4 ka = *(const float4*)&ska[h][tx * 4];
            float qv[2] = {qb.x, qb.y};
            float kv[4] = {ka.x, ka.y, ka.z, ka.w};
            #pragma unroll
            for (int i = 0; i < 2; i++)
                #pragma unroll
                for (int j = 0; j < 4; j++)
                    acc[i][j] += fmaxf(kv[j] + qv[i], 0.f) * w;
        }
    }

    float* outp = lg + (long)hq * LGSZ;
    #pragma unroll
    for (int i = 0; i < 2; i++) {
        int q = q0 + ty * 2 + i;
        #pragma unroll
        for (int j = 0; j < 4; j++) {
            int k = k0 + tx * 4 + j;
            outp[((long)b * SEQ + q) * SEQ + k] = acc[i][j];
        }
    }
}

// ---------------- masked softmax; sums 4 H-partials; sym adds transpose ----
__global__ void softmax_kernel(const float* __restrict__ lg,
                               const float* __restrict__ mask, const float* __restrict__ b2p,
                               float* __restrict__ probs, int sym)
{
    int q = blockIdx.x, b = blockIdx.y;
    long row = ((long)b * SEQ + q) * SEQ;
    int t = threadIdx.x;
    __shared__ float red[8];

    float x = 0.f;
    #pragma unroll
    for (int p = 0; p < 4; p++) x += lg[(long)p * LGSZ + row + t];
    if (sym) {
        long col = ((long)b * SEQ + t) * SEQ + q;
        #pragma unroll
        for (int p = 0; p < 4; p++) x += lg[(long)p * LGSZ + col];
    }
    x += 2.f * b2p[0] + mask[row + t] * (-1e9f);

    float m = x;
    #pragma unroll
    for (int o = 16; o; o >>= 1) m = fmaxf(m, __shfl_xor_sync(0xffffffffu, m, o));
    if ((t & 31) == 0) red[t >> 5] = m;
    __syncthreads();
    m = red[0];
    #pragma unroll
    for (int i = 1; i < 8; i++) m = fmaxf(m, red[i]);

    float e = __expf(x - m);
    float s = e;
    #pragma unroll
    for (int o = 16; o; o >>= 1) s += __shfl_xor_sync(0xffffffffu, s, o);
    __syncthreads();
    if ((t & 31) == 0) red[t >> 5] = s;
    __syncthreads();
    s = red[0] + red[1] + red[2] + red[3] + red[4] + red[5] + red[6] + red[7];
    probs[row + t] = e / s;
}

// ---------------- fused GEMM + bias + residual + LayerNorm -----------------
// out[m,:] = LN( A[m,:K] @ B + bias + res[m,:] ), N=128. 8 rows/block.
// B base advances by sBb per 256-row batch of output rows (0 = shared B).
__global__ void gemm_ln_kernel(const float* __restrict__ A, int lda,
                               const float* __restrict__ B, long sBb,
                               const float* __restrict__ bias, const float* __restrict__ res,
                               const float* __restrict__ g, const float* __restrict__ be,
                               float* __restrict__ out, int K)
{
    __shared__ float As[32][12];     // [k][m]
    __shared__ float Bs[32][132];    // [k][n]
    int m0 = blockIdx.x * 8;
    const float* Bb = B + (long)(m0 >> 8) * sBb;
    int tid = threadIdx.x;
    int tr = tid >> 5, tc = tid & 31;    // warp tr owns row m0+tr; lanes = 128 cols
    float acc[4] = {};

    for (int k0 = 0; k0 < K; k0 += 32) {
        {
            int k = tid & 31, mm = tid >> 5;
            As[k][mm] = A[(long)(m0 + mm) * lda + k0 + k];
        }
        #pragma unroll
        for (int i = 0; i < 4; i++) {
            int idx = tid + i * 256;
            int n4 = idx & 31, kb = idx >> 5;
            *(float4*)&Bs[kb][n4 * 4] = *(const float4*)&Bb[(long)(k0 + kb) * 128 + n4 * 4];
        }
        __syncthreads();
        #pragma unroll
        for (int kk = 0; kk < 32; kk++) {
            float a = As[kk][tr];
            float4 b = *(const float4*)&Bs[kk][tc * 4];
            acc[0] += a * b.x; acc[1] += a * b.y;
            acc[2] += a * b.z; acc[3] += a * b.w;
        }
        __syncthreads();
    }

    int r = m0 + tr;
    float v[4];
    #pragma unroll
    for (int j = 0; j < 4; j++) {
        int n = tc * 4 + j;
        v[j] = acc[j] + bias[n] + res[(long)r * 128 + n];
    }
    float s = v[0] + v[1] + v[2] + v[3];
    #pragma unroll
    for (int o = 16; o; o >>= 1) s += __shfl_xor_sync(0xffffffffu, s, o);
    float mean = s * (1.f / 128.f);
    float vs = 0.f;
    #pragma unroll
    for (int j = 0; j < 4; j++) { float d = v[j] - mean; vs += d * d; }
    #pragma unroll
    for (int o = 16; o; o >>= 1) vs += __shfl_xor_sync(0xffffffffu, vs, o);
    float inv = rsqrtf(vs * (1.f / 128.f) + 1e-6f);
    #pragma unroll
    for (int j = 0; j < 4; j++) {
        int n = tc * 4 + j;
        out[(long)r * 128 + n] = (v[j] - mean) * inv * g[n] + be[n];
    }
}

// ---------------- host orchestration ----------------
extern "C" void kernel_launch(void* const* d_in, const int* in_sizes, int n_in,
                              void* d_out, int out_size)
{
    (void)in_sizes; (void)n_in; (void)out_size;
    const float* x    = (const float*)d_in[0];
    const float* enc  = (const float*)d_in[1];
    const float* cmsk = (const float*)d_in[2];
    const float* dmsk = (const float*)d_in[3];
    const float* W1q  = (const float*)d_in[4];
    const float* W1k  = (const float*)d_in[5];
    const float* b1   = (const float*)d_in[6];
    const float* W2   = (const float*)d_in[7];
    const float* b2   = (const float*)d_in[8];
    const float* Ww1  = (const float*)d_in[9];
    const float* bw1  = (const float*)d_in[10];
    const float* Wd1  = (const float*)d_in[11];
    const float* bd1  = (const float*)d_in[12];
    const float* Ww2  = (const float*)d_in[13];
    const float* bw2  = (const float*)d_in[14];
    const float* Wd2  = (const float*)d_in[15];
    const float* bd2  = (const float*)d_in[16];
    const float* Wf1  = (const float*)d_in[17];
    const float* bf1  = (const float*)d_in[18];
    const float* Wf2  = (const float*)d_in[19];
    const float* bf2  = (const float*)d_in[20];
    const float* ln1g = (const float*)d_in[21];
    const float* ln1b = (const float*)d_in[22];
    const float* ln2g = (const float*)d_in[23];
    const float* ln2b = (const float*)d_in[24];
    const float* ln3g = (const float*)d_in[25];
    const float* ln3b = (const float*)d_in[26];
    float* out = (float*)d_out;

    float *Wb1, *Wb2, *bb1, *bb2, *buf1, *buf2, *Tq, *vw, *lg, *probs, *o1, *o2, *fh;
    cudaGetSymbolAddress((void**)&Wb1,   g_Wbig1);
    cudaGetSymbolAddress((void**)&Wb2,   g_Wbig2);
    cudaGetSymbolAddress((void**)&bb1,   g_bbig1);
    cudaGetSymbolAddress((void**)&bb2,   g_bbig2);
    cudaGetSymbolAddress((void**)&buf1,  g_buf1);
    cudaGetSymbolAddress((void**)&buf2,  g_buf2);
    cudaGetSymbolAddress((void**)&Tq,    g_Tq);
    cudaGetSymbolAddress((void**)&vw,    g_vw);
    cudaGetSymbolAddress((void**)&lg,    g_lg);
    cudaGetSymbolAddress((void**)&probs, g_probs);
    cudaGetSymbolAddress((void**)&o1,    g_o1);
    cudaGetSymbolAddress((void**)&o2,    g_o2);
    cudaGetSymbolAddress((void**)&fh,    g_fh);

    dim3 simGrid(SEQ / 64, SEQ / 32, BSZ * 4);   // 512 blocks
    dim3 smGrid(SEQ, BSZ);

    // ---- prep (weights only) ----
    prep_bias_kernel<<<dim3(32, 2), 256>>>(bw1, bw2, W1q, W1k, b1, bb1, bb2);
    prep_wbig_kernel<<<dim3(12, 4, 2), 256>>>(Ww1, Ww2, W1q, W1k, Wb1, Wb2);

    // ---- batched projection: buf1 = x@Wbig1+bbig1, buf2 = enc@Wbig2+bbig2 ----
    sgemm2x4_kernel<<<dim3(6, 32, 2), 256>>>(x, Wb1, bb1, buf1,
                                             enc, Wb2, bb2, buf2,
                                             128, 128, 384, 384, 0);

    // ---- batched VW = V @ Wd (both attention blocks) ----
    vw_kernel<<<dim3(4, 8, 8), 256>>>(buf1, buf2, Wd1, Wd2, vw);

    // ---- self-attention: logits = S + S^T (symmetry) ----
    sim_kernel<<<simGrid, 256>>>(buf1 + 128, 384, buf1 + 128, 384, W2, lg, 0);
    softmax_kernel<<<smGrid, 256>>>(lg, cmsk, b2, probs, 1);
    gemm_ln_kernel<<<MROWS / 8, 256>>>(probs, 256, vw, (long)SEQ * DIM,
                                       bd1, x, ln1g, ln1b, o1, 256);

    // ---- cross-attention ----
    sgemm2x4_kernel<<<dim3(4, 32, 1), 256>>>(o1, Wb2 + 128, bb2 + 128, Tq,
                                             0, 0, 0, 0,
                                             128, 128, 384, 256, 0);
    sim_kernel<<<simGrid, 256>>>(Tq, 256, buf2 + 128, 384, W2, lg, 1);
    softmax_kernel<<<smGrid, 256>>>(lg, dmsk, b2, probs, 0);
    gemm_ln_kernel<<<MROWS / 8, 256>>>(probs, 256, vw + (long)MROWS * DIM, (long)SEQ * DIM,
                                       bd2, o1, ln2g, ln2b, o2, 256);

    // ---- FFN ----
    sgemm2x4_kernel<<<dim3(8, 32, 1), 256>>>(o2, Wf1, bf1, fh, 0, 0, 0, 0,
                                             128, 128, 512, 512, 1);
    gemm_ln_kernel<<<MROWS / 8, 256>>>(fh, 512, Wf2, 0,
                                       bf2, o2, ln3g, ln3b, out, 512);
}

// round 7
// speedup vs baseline: 1.0023x; 1.0023x over previous
#include <cuda_runtime.h>

#define BSZ 4
#define SEQ 256
#define DIM 128
#define HID 128
#define DFF 512
#define MROWS (BSZ*SEQ)   // 1024
#define LGSZ (BSZ*SEQ*SEQ)

// ---------------- scratch (device globals; no allocations) ----------------
__device__ float g_Wbig1[DIM*384];    // [Ww1@W1q | Ww1@W1k | Ww1@Wd1]
__device__ float g_Wbig2[DIM*384];    // [Ww2@W1q | Ww2@W1k | Ww2@Wd2]
__device__ float g_bbig1[384];        // [bw1@W1q+b1 | bw1@W1k | bw1@Wd1]
__device__ float g_bbig2[384];
__device__ float g_buf1[MROWS*384];   // [T1A | T1B | VW1]
__device__ float g_buf2[MROWS*384];   // [TkA | TkB | VW2]
__device__ float g_Tq  [MROWS*256];   // [TqA | TqB]
__device__ float g_lg  [4*LGSZ];      // sim partials (4 H-quarters)
__device__ float g_probs[LGSZ];
__device__ float g_o1 [MROWS*DIM];
__device__ float g_o2 [MROWS*DIM];
__device__ float g_fh [MROWS*DFF];

// ---------------- prep: bbig = [bw@W1q + b1 | bw@W1k | bw@Wd] --------------
// grid (48, 2), 256 thr; warp per output column.
__global__ void prep_bias_kernel(const float* __restrict__ bw1, const float* __restrict__ bw2,
                                 const float* __restrict__ W1q, const float* __restrict__ W1k,
                                 const float* __restrict__ Wd1, const float* __restrict__ Wd2,
                                 const float* __restrict__ b1,
                                 float* __restrict__ bbig1, float* __restrict__ bbig2)
{
    const float* bw = blockIdx.y ? bw2 : bw1;
    const float* Wd = blockIdx.y ? Wd2 : Wd1;
    float* outp = blockIdx.y ? bbig2 : bbig1;
    int tid = threadIdx.x;
    int np = blockIdx.x * 8 + (tid >> 5);   // 0..383
    int lane = tid & 31;
    int grp = np >> 7;                      // 0:W1q 1:W1k 2:Wd
    const float* Wsrc = (grp == 0) ? W1q : (grp == 1) ? W1k : Wd;
    int col = np & 127;
    float s = 0.f;
    #pragma unroll
    for (int i = 0; i < 4; i++) {
        int k = lane + 32 * i;
        s += bw[k] * Wsrc[k * 128 + col];
    }
    #pragma unroll
    for (int o = 16; o; o >>= 1) s += __shfl_xor_sync(0xffffffffu, s, o);
    if (lane == 0) {
        if (grp == 0) s += b1[col];
        outp[np] = s;
    }
}

// ---------------- prep: Wbig = [Ww@W1q | Ww@W1k | Ww@Wd]  (128x384) --------
__global__ void prep_wbig_kernel(const float* __restrict__ Ww1, const float* __restrict__ Ww2,
                                 const float* __restrict__ W1q, const float* __restrict__ W1k,
                                 const float* __restrict__ Wd1, const float* __restrict__ Wd2,
                                 float* __restrict__ Wbig1, float* __restrict__ Wbig2)
{
    const float* Ww = blockIdx.z ? Ww2 : Ww1;
    const float* Wd = blockIdx.z ? Wd2 : Wd1;
    float* Wbig = blockIdx.z ? Wbig2 : Wbig1;
    int n0p = blockIdx.x * 32;             // 0..352
    int m0 = blockIdx.y * 32;
    int grp = n0p >> 7;
    const float* Bsrc = ((grp == 0) ? W1q : (grp == 1) ? W1k : Wd) + (n0p & 127);
    __shared__ float As[32][34], Bs[32][34];
    int tid = threadIdx.x;
    int tx = tid & 15, ty = tid >> 4;
    float a00 = 0.f, a01 = 0.f, a10 = 0.f, a11 = 0.f;
    for (int k0 = 0; k0 < 128; k0 += 32) {
        #pragma unroll
        for (int i = 0; i < 4; i++) {
            int idx = tid + i * 256;
            int ka = idx & 31, ma = idx >> 5;
            As[ka][ma] = Ww[(m0 + ma) * 128 + k0 + ka];
            int nb = idx & 31, kb = idx >> 5;
            Bs[kb][nb] = Bsrc[(k0 + kb) * 128 + nb];
        }
        __syncthreads();
        #pragma unroll
        for (int kk = 0; kk < 32; kk++) {
            float2 a = *(const float2*)&As[kk][ty * 2];
            float2 b = *(const float2*)&Bs[kk][tx * 2];
            a00 += a.x * b.x; a01 += a.x * b.y;
            a10 += a.y * b.x; a11 += a.y * b.y;
        }
        __syncthreads();
    }
    int m = m0 + ty * 2, n = n0p + tx * 2;
    Wbig[m * 384 + n]           = a00;
    Wbig[m * 384 + n + 1]       = a01;
    Wbig[(m + 1) * 384 + n]     = a10;
    Wbig[(m + 1) * 384 + n + 1] = a11;
}

// ---------------- SGEMM 32x64 tile, 256 thr, 2x4 micro ---------------------
__global__ void sgemm2x4_kernel(const float* __restrict__ A0, const float* __restrict__ B0,
                                const float* __restrict__ bias0, float* __restrict__ C0,
                                const float* __restrict__ A1, const float* __restrict__ B1,
                                const float* __restrict__ bias1, float* __restrict__ C1,
                                int K, int lda, int ldb, int ldc, int relu)
{
    __shared__ float As[32][34];
    __shared__ float Bs[32][68];
    int z = blockIdx.z;
    bool use1 = (z == 1) && (C1 != 0);
    const float* A = use1 ? A1 : A0;
    const float* B = use1 ? B1 : B0;
    const float* bias = use1 ? bias1 : bias0;
    float* C = use1 ? C1 : C0;
    int m0 = blockIdx.y * 32, n0 = blockIdx.x * 64;
    int tid = threadIdx.x;
    int tx = tid & 15, ty = tid >> 4;
    float acc[2][4] = {};

    for (int k0 = 0; k0 < K; k0 += 32) {
        #pragma unroll
        for (int i = 0; i < 4; i++) {          // A: 32m x 32k
            int idx = tid + i * 256;
            int ka = idx & 31, ma = idx >> 5;
            As[ka][ma] = A[(long)(m0 + ma) * lda + k0 + ka];
        }
        #pragma unroll
        for (int i = 0; i < 8; i++) {          // B: 32k x 64n
            int idx = tid + i * 256;
            int nb = idx & 63, kb = idx >> 6;
            Bs[kb][nb] = B[(long)(k0 + kb) * ldb + n0 + nb];
        }
        __syncthreads();
        #pragma unroll
        for (int kk = 0; kk < 32; kk++) {
            float2 a = *(const float2*)&As[kk][ty * 2];
            float4 b = *(const float4*)&Bs[kk][tx * 4];
            float bv[4] = {b.x, b.y, b.z, b.w};
            #pragma unroll
            for (int j = 0; j < 4; j++) {
                acc[0][j] += a.x * bv[j];
                acc[1][j] += a.y * bv[j];
            }
        }
        __syncthreads();
    }
    int m = m0 + ty * 2, n = n0 + tx * 4;
    float bb[4] = {0.f, 0.f, 0.f, 0.f};
    if (bias) {
        #pragma unroll
        for (int j = 0; j < 4; j++) bb[j] = bias[n + j];
    }
    #pragma unroll
    for (int i = 0; i < 2; i++) {
        float4 o4;
        float v0 = acc[i][0] + bb[0], v1 = acc[i][1] + bb[1];
        float v2 = acc[i][2] + bb[2], v3 = acc[i][3] + bb[3];
        if (relu) { v0=fmaxf(v0,0.f); v1=fmaxf(v1,0.f); v2=fmaxf(v2,0.f); v3=fmaxf(v3,0.f); }
        o4.x=v0; o4.y=v1; o4.z=v2; o4.w=v3;
        *(float4*)&C[(long)(m + i) * ldc + n] = o4;
    }
}

// ---------------- pairwise similarity (proven) -----------------------------
// q rows at qbase (stride ldq): A-part +0, B-part +128; same layout at kbase.
__global__ void sim_kernel(const float* __restrict__ qbase, int ldq,
                           const float* __restrict__ kbase, int ldk,
                           const float* __restrict__ W2,
                           float* __restrict__ lg, int dual)
{
    __shared__ float sqa[32][34];
    __shared__ float sqb[32][34];
    __shared__ float skb[32][68];
    __shared__ float ska[32][68];
    __shared__ float sw[32];

    int z = blockIdx.z, b = z >> 2, hq = z & 3;
    int h0 = hq * 32;
    int q0 = blockIdx.y * 32, k0 = blockIdx.x * 64;
    const float* qp = qbase + (long)(b * SEQ + q0) * ldq;
    const float* kp = kbase + (long)(b * SEQ + k0) * ldk;
    int tid = threadIdx.x;
    int tx = tid & 15, ty = tid >> 4;
    float acc[2][4] = {};

    #pragma unroll
    for (int i = 0; i < 4; i++) {
        int idx = tid + i * 256;
        int r = idx >> 5, h = idx & 31;
        sqa[h][r] = qp[(long)r * ldq + h0 + h];
        if (dual) sqb[h][r] = qp[(long)r * ldq + 128 + h0 + h];
    }
    #pragma unroll
    for (int i = 0; i < 8; i++) {
        int idx = tid + i * 256;
        int r = idx >> 5, h = idx & 31;
        skb[h][r] = kp[(long)r * ldk + 128 + h0 + h];
        if (dual) ska[h][r] = kp[(long)r * ldk + h0 + h];
    }
    if (tid < 32) sw[tid] = W2[h0 + tid];
    __syncthreads();

    #pragma unroll 4
    for (int h = 0; h < 32; h++) {
        float w = sw[h];
        float2 a1r = *(const float2*)&sqa[h][ty * 2];
        float4 b1r = *(const float4*)&skb[h][tx * 4];
        float a1v[2] = {a1r.x, a1r.y};
        float b1v[4] = {b1r.x, b1r.y, b1r.z, b1r.w};
        #pragma unroll
        for (int i = 0; i < 2; i++)
            #pragma unroll
            for (int j = 0; j < 4; j++)
                acc[i][j] += fmaxf(a1v[i] + b1v[j], 0.f) * w;
        if (dual) {
            float2 qb = *(const float2*)&sqb[h][ty * 2];
            float4 ka = *(const float4*)&ska[h][tx * 4];
            float qv[2] = {qb.x, qb.y};
            float kv[4] = {ka.x, ka.y, ka.z, ka.w};
            #pragma unroll
            for (int i = 0; i < 2; i++)
                #pragma unroll
                for (int j = 0; j < 4; j++)
                    acc[i][j] += fmaxf(kv[j] + qv[i], 0.f) * w;
        }
    }

    float* outp = lg + (long)hq * LGSZ;
    #pragma unroll
    for (int i = 0; i < 2; i++) {
        int q = q0 + ty * 2 + i;
        #pragma unroll
        for (int j = 0; j < 4; j++) {
            int k = k0 + tx * 4 + j;
            outp[((long)b * SEQ + q) * SEQ + k] = acc[i][j];
        }
    }
}

// ---------------- masked softmax; sums 4 H-partials; sym adds transpose ----
__global__ void softmax_kernel(const float* __restrict__ lg,
                               const float* __restrict__ mask, const float* __restrict__ b2p,
                               float* __restrict__ probs, int sym)
{
    int q = blockIdx.x, b = blockIdx.y;
    long row = ((long)b * SEQ + q) * SEQ;
    int t = threadIdx.x;
    __shared__ float red[8];

    float x = 0.f;
    #pragma unroll
    for (int p = 0; p < 4; p++) x += lg[(long)p * LGSZ + row + t];
    if (sym) {
        long col = ((long)b * SEQ + t) * SEQ + q;
        #pragma unroll
        for (int p = 0; p < 4; p++) x += lg[(long)p * LGSZ + col];
    }
    x += 2.f * b2p[0] + mask[row + t] * (-1e9f);

    float m = x;
    #pragma unroll
    for (int o = 16; o; o >>= 1) m = fmaxf(m, __shfl_xor_sync(0xffffffffu, m, o));
    if ((t & 31) == 0) red[t >> 5] = m;
    __syncthreads();
    m = red[0];
    #pragma unroll
    for (int i = 1; i < 8; i++) m = fmaxf(m, red[i]);

    float e = __expf(x - m);
    float s = e;
    #pragma unroll
    for (int o = 16; o; o >>= 1) s += __shfl_xor_sync(0xffffffffu, s, o);
    __syncthreads();
    if ((t & 31) == 0) red[t >> 5] = s;
    __syncthreads();
    s = red[0] + red[1] + red[2] + red[3] + red[4] + red[5] + red[6] + red[7];
    probs[row + t] = e / s;
}

// ---------------- fused GEMM + bias + residual + LayerNorm -----------------
// out[m,:] = LN( A[m,:K] @ B + bias + res[m,:] ), N=128. 8 rows/block.
// B has row-stride ldb; B base advances by sBb per 256 output rows.
__global__ void gemm_ln_kernel(const float* __restrict__ A, int lda,
                               const float* __restrict__ B, int ldb, long sBb,
                               const float* __restrict__ bias, const float* __restrict__ res,
                               const float* __restrict__ g, const float* __restrict__ be,
                               float* __restrict__ out, int K)
{
    __shared__ float As[32][12];     // [k][m]
    __shared__ float Bs[32][132];    // [k][n]
    int m0 = blockIdx.x * 8;
    const float* Bb = B + (long)(m0 >> 8) * sBb;
    int tid = threadIdx.x;
    int tr = tid >> 5, tc = tid & 31;
    float acc[4] = {};

    for (int k0 = 0; k0 < K; k0 += 32) {
        {
            int k = tid & 31, mm = tid >> 5;
            As[k][mm] = A[(long)(m0 + mm) * lda + k0 + k];
        }
        #pragma unroll
        for (int i = 0; i < 4; i++) {
            int idx = tid + i * 256;
            int n4 = idx & 31, kb = idx >> 5;
            *(float4*)&Bs[kb][n4 * 4] = *(const float4*)&Bb[(long)(k0 + kb) * ldb + n4 * 4];
        }
        __syncthreads();
        #pragma unroll
        for (int kk = 0; kk < 32; kk++) {
            float a = As[kk][tr];
            float4 b = *(const float4*)&Bs[kk][tc * 4];
            acc[0] += a * b.x; acc[1] += a * b.y;
            acc[2] += a * b.z; acc[3] += a * b.w;
        }
        __syncthreads();
    }

    int r = m0 + tr;
    float v[4];
    #pragma unroll
    for (int j = 0; j < 4; j++) {
        int n = tc * 4 + j;
        v[j] = acc[j] + bias[n] + res[(long)r * 128 + n];
    }
    float s = v[0] + v[1] + v[2] + v[3];
    #pragma unroll
    for (int o = 16; o; o >>= 1) s += __shfl_xor_sync(0xffffffffu, s, o);
    float mean = s * (1.f / 128.f);
    float vs = 0.f;
    #pragma unroll
    for (int j = 0; j < 4; j++) { float d = v[j] - mean; vs += d * d; }
    #pragma unroll
    for (int o = 16; o; o >>= 1) vs += __shfl_xor_sync(0xffffffffu, vs, o);
    float inv = rsqrtf(vs * (1.f / 128.f) + 1e-6f);
    #pragma unroll
    for (int j = 0; j < 4; j++) {
        int n = tc * 4 + j;
        out[(long)r * 128 + n] = (v[j] - mean) * inv * g[n] + be[n];
    }
}

// ---------------- host orchestration ----------------
extern "C" void kernel_launch(void* const* d_in, const int* in_sizes, int n_in,
                              void* d_out, int out_size)
{
    (void)in_sizes; (void)n_in; (void)out_size;
    const float* x    = (const float*)d_in[0];
    const float* enc  = (const float*)d_in[1];
    const float* cmsk = (const float*)d_in[2];
    const float* dmsk = (const float*)d_in[3];
    const float* W1q  = (const float*)d_in[4];
    const float* W1k  = (const float*)d_in[5];
    const float* b1   = (const float*)d_in[6];
    const float* W2   = (const float*)d_in[7];
    const float* b2   = (const float*)d_in[8];
    const float* Ww1  = (const float*)d_in[9];
    const float* bw1  = (const float*)d_in[10];
    const float* Wd1  = (const float*)d_in[11];
    const float* bd1  = (const float*)d_in[12];
    const float* Ww2  = (const float*)d_in[13];
    const float* bw2  = (const float*)d_in[14];
    const float* Wd2  = (const float*)d_in[15];
    const float* bd2  = (const float*)d_in[16];
    const float* Wf1  = (const float*)d_in[17];
    const float* bf1  = (const float*)d_in[18];
    const float* Wf2  = (const float*)d_in[19];
    const float* bf2  = (const float*)d_in[20];
    const float* ln1g = (const float*)d_in[21];
    const float* ln1b = (const float*)d_in[22];
    const float* ln2g = (const float*)d_in[23];
    const float* ln2b = (const float*)d_in[24];
    const float* ln3g = (const float*)d_in[25];
    const float* ln3b = (const float*)d_in[26];
    float* out = (float*)d_out;

    float *Wb1, *Wb2, *bb1, *bb2, *buf1, *buf2, *Tq, *lg, *probs, *o1, *o2, *fh;
    cudaGetSymbolAddress((void**)&Wb1,   g_Wbig1);
    cudaGetSymbolAddress((void**)&Wb2,   g_Wbig2);
    cudaGetSymbolAddress((void**)&bb1,   g_bbig1);
    cudaGetSymbolAddress((void**)&bb2,   g_bbig2);
    cudaGetSymbolAddress((void**)&buf1,  g_buf1);
    cudaGetSymbolAddress((void**)&buf2,  g_buf2);
    cudaGetSymbolAddress((void**)&Tq,    g_Tq);
    cudaGetSymbolAddress((void**)&lg,    g_lg);
    cudaGetSymbolAddress((void**)&probs, g_probs);
    cudaGetSymbolAddress((void**)&o1,    g_o1);
    cudaGetSymbolAddress((void**)&o2,    g_o2);
    cudaGetSymbolAddress((void**)&fh,    g_fh);

    dim3 simGrid(SEQ / 64, SEQ / 32, BSZ * 4);   // 512 blocks
    dim3 smGrid(SEQ, BSZ);

    // ---- prep (weights only) ----
    prep_bias_kernel<<<dim3(48, 2), 256>>>(bw1, bw2, W1q, W1k, Wd1, Wd2, b1, bb1, bb2);
    prep_wbig_kernel<<<dim3(12, 4, 2), 256>>>(Ww1, Ww2, W1q, W1k, Wd1, Wd2, Wb1, Wb2);

    // ---- batched projection: buf = [TA | TB | VW] for x and enc ----
    sgemm2x4_kernel<<<dim3(6, 32, 2), 256>>>(x, Wb1, bb1, buf1,
                                             enc, Wb2, bb2, buf2,
                                             128, 128, 384, 384, 0);

    // ---- self-attention: logits = S + S^T (symmetry) ----
    sim_kernel<<<simGrid, 256>>>(buf1, 384, buf1, 384, W2, lg, 0);
    softmax_kernel<<<smGrid, 256>>>(lg, cmsk, b2, probs, 1);
    gemm_ln_kernel<<<MROWS / 8, 256>>>(probs, 256, buf1 + 256, 384, (long)SEQ * 384,
                                       bd1, x, ln1g, ln1b, o1, 256);

    // ---- cross-attention: Tq = o1 @ Wbig2[:,0:256] + bbig2[0:256] ----
    sgemm2x4_kernel<<<dim3(4, 32, 1), 256>>>(o1, Wb2, bb2, Tq,
                                             0, 0, 0, 0,
                                             128, 128, 384, 256, 0);
    sim_kernel<<<simGrid, 256>>>(Tq, 256, buf2, 384, W2, lg, 1);
    softmax_kernel<<<smGrid, 256>>>(lg, dmsk, b2, probs, 0);
    gemm_ln_kernel<<<MROWS / 8, 256>>>(probs, 256, buf2 + 256, 384, (long)SEQ * 384,
                                       bd2, o1, ln2g, ln2b, o2, 256);

    // ---- FFN ----
    sgemm2x4_kernel<<<dim3(8, 32, 1), 256>>>(o2, Wf1, bf1, fh, 0, 0, 0, 0,
                                             128, 128, 512, 512, 1);
    gemm_ln_kernel<<<MROWS / 8, 256>>>(fh, 512, Wf2, 128, 0,
                                       bf2, o2, ln3g, ln3b, out, 512);
}

// round 8
// speedup vs baseline: 1.1134x; 1.1108x over previous
#include <cuda_runtime.h>

#define BSZ 4
#define SEQ 256
#define DIM 128
#define HID 128
#define DFF 512
#define MROWS (BSZ*SEQ)   // 1024
#define LGSZ (BSZ*SEQ*SEQ)

// ---------------- scratch (device globals; no allocations) ----------------
__device__ float g_Wbig1[DIM*384];    // [Ww1@W1q | Ww1@W1k | Ww1@Wd1]
__device__ float g_Wbig2[DIM*384];
__device__ float g_bbig1[384];        // [bw1@W1q+b1 | bw1@W1k | bw1@Wd1]
__device__ float g_bbig2[384];
__device__ float g_buf1[MROWS*384];   // [T1A | T1B | VW1]
__device__ float g_buf2[MROWS*384];   // [TkA | TkB | VW2]
__device__ float g_Tq  [MROWS*256];   // [TqA | TqB]
__device__ float g_lg  [4*LGSZ];      // sim partials (4 H-quarters)
__device__ float g_o1 [MROWS*DIM];
__device__ float g_o2 [MROWS*DIM];
__device__ float g_fh [MROWS*DFF];

// ---------------- prep: Wbig tiles (y<4) + bbig (y==4), both sets (z) ------
__global__ void prep_kernel(const float* __restrict__ Ww1, const float* __restrict__ Ww2,
                            const float* __restrict__ W1q, const float* __restrict__ W1k,
                            const float* __restrict__ Wd1, const float* __restrict__ Wd2,
                            const float* __restrict__ bw1, const float* __restrict__ bw2,
                            const float* __restrict__ b1,
                            float* __restrict__ Wbig1, float* __restrict__ Wbig2,
                            float* __restrict__ bbig1, float* __restrict__ bbig2)
{
    const float* Ww = blockIdx.z ? Ww2 : Ww1;
    const float* Wd = blockIdx.z ? Wd2 : Wd1;
    const float* bw = blockIdx.z ? bw2 : bw1;
    float* Wbig = blockIdx.z ? Wbig2 : Wbig1;
    float* bbig = blockIdx.z ? bbig2 : bbig1;
    int n0p = blockIdx.x * 32;             // 0..352
    int grp = n0p >> 7;                    // 0:W1q 1:W1k 2:Wd
    const float* Bsrc = ((grp == 0) ? W1q : (grp == 1) ? W1k : Wd) + (n0p & 127);
    int tid = threadIdx.x;

    if (blockIdx.y == 4) {                 // bias row: bbig[n0p .. n0p+32)
        int w = tid >> 5, lane = tid & 31;
        for (int c = w; c < 32; c += 8) {
            int np = n0p + c;
            float s = 0.f;
            #pragma unroll
            for (int i = 0; i < 4; i++) {
                int k = lane + 32 * i;
                s += bw[k] * Bsrc[k * 128 + c];
            }
            #pragma unroll
            for (int o = 16; o; o >>= 1) s += __shfl_xor_sync(0xffffffffu, s, o);
            if (lane == 0) {
                if (grp == 0) s += b1[np & 127];
                bbig[np] = s;
            }
        }
        return;
    }

    int m0 = blockIdx.y * 32;
    __shared__ float As[32][34], Bs[32][34];
    int tx = tid & 15, ty = tid >> 4;
    float a00 = 0.f, a01 = 0.f, a10 = 0.f, a11 = 0.f;
    for (int k0 = 0; k0 < 128; k0 += 32) {
        #pragma unroll
        for (int i = 0; i < 4; i++) {
            int idx = tid + i * 256;
            int ka = idx & 31, ma = idx >> 5;
            As[ka][ma] = Ww[(m0 + ma) * 128 + k0 + ka];
            int nb = idx & 31, kb = idx >> 5;
            Bs[kb][nb] = Bsrc[(k0 + kb) * 128 + nb];
        }
        __syncthreads();
        #pragma unroll
        for (int kk = 0; kk < 32; kk++) {
            float2 a = *(const float2*)&As[kk][ty * 2];
            float2 b = *(const float2*)&Bs[kk][tx * 2];
            a00 += a.x * b.x; a01 += a.x * b.y;
            a10 += a.y * b.x; a11 += a.y * b.y;
        }
        __syncthreads();
    }
    int m = m0 + ty * 2, n = n0p + tx * 2;
    Wbig[m * 384 + n]           = a00;
    Wbig[m * 384 + n + 1]       = a01;
    Wbig[(m + 1) * 384 + n]     = a10;
    Wbig[(m + 1) * 384 + n + 1] = a11;
}

// ---------------- SGEMM 32x64 tile, 256 thr, 2x4 micro ---------------------
__global__ void sgemm2x4_kernel(const float* __restrict__ A0, const float* __restrict__ B0,
                                const float* __restrict__ bias0, float* __restrict__ C0,
                                const float* __restrict__ A1, const float* __restrict__ B1,
                                const float* __restrict__ bias1, float* __restrict__ C1,
                                int K, int lda, int ldb, int ldc, int relu)
{
    __shared__ float As[32][34];
    __shared__ float Bs[32][68];
    int z = blockIdx.z;
    bool use1 = (z == 1) && (C1 != 0);
    const float* A = use1 ? A1 : A0;
    const float* B = use1 ? B1 : B0;
    const float* bias = use1 ? bias1 : bias0;
    float* C = use1 ? C1 : C0;
    int m0 = blockIdx.y * 32, n0 = blockIdx.x * 64;
    int tid = threadIdx.x;
    int tx = tid & 15, ty = tid >> 4;
    float acc[2][4] = {};

    for (int k0 = 0; k0 < K; k0 += 32) {
        #pragma unroll
        for (int i = 0; i < 4; i++) {
            int idx = tid + i * 256;
            int ka = idx & 31, ma = idx >> 5;
            As[ka][ma] = A[(long)(m0 + ma) * lda + k0 + ka];
        }
        #pragma unroll
        for (int i = 0; i < 8; i++) {
            int idx = tid + i * 256;
            int nb = idx & 63, kb = idx >> 6;
            Bs[kb][nb] = B[(long)(k0 + kb) * ldb + n0 + nb];
        }
        __syncthreads();
        #pragma unroll
        for (int kk = 0; kk < 32; kk++) {
            float2 a = *(const float2*)&As[kk][ty * 2];
            float4 b = *(const float4*)&Bs[kk][tx * 4];
            float bv[4] = {b.x, b.y, b.z, b.w};
            #pragma unroll
            for (int j = 0; j < 4; j++) {
                acc[0][j] += a.x * bv[j];
                acc[1][j] += a.y * bv[j];
            }
        }
        __syncthreads();
    }
    int m = m0 + ty * 2, n = n0 + tx * 4;
    float bb[4] = {0.f, 0.f, 0.f, 0.f};
    if (bias) {
        #pragma unroll
        for (int j = 0; j < 4; j++) bb[j] = bias[n + j];
    }
    #pragma unroll
    for (int i = 0; i < 2; i++) {
        float4 o4;
        float v0 = acc[i][0] + bb[0], v1 = acc[i][1] + bb[1];
        float v2 = acc[i][2] + bb[2], v3 = acc[i][3] + bb[3];
        if (relu) { v0=fmaxf(v0,0.f); v1=fmaxf(v1,0.f); v2=fmaxf(v2,0.f); v3=fmaxf(v3,0.f); }
        o4.x=v0; o4.y=v1; o4.z=v2; o4.w=v3;
        *(float4*)&C[(long)(m + i) * ldc + n] = o4;
    }
}

// ---------------- pairwise similarity (proven) -----------------------------
__global__ void sim_kernel(const float* __restrict__ qbase, int ldq,
                           const float* __restrict__ kbase, int ldk,
                           const float* __restrict__ W2,
                           float* __restrict__ lg, int dual)
{
    __shared__ float sqa[32][34];
    __shared__ float sqb[32][34];
    __shared__ float skb[32][68];
    __shared__ float ska[32][68];
    __shared__ float sw[32];

    int z = blockIdx.z, b = z >> 2, hq = z & 3;
    int h0 = hq * 32;
    int q0 = blockIdx.y * 32, k0 = blockIdx.x * 64;
    const float* qp = qbase + (long)(b * SEQ + q0) * ldq;
    const float* kp = kbase + (long)(b * SEQ + k0) * ldk;
    int tid = threadIdx.x;
    int tx = tid & 15, ty = tid >> 4;
    float acc[2][4] = {};

    #pragma unroll
    for (int i = 0; i < 4; i++) {
        int idx = tid + i * 256;
        int r = idx >> 5, h = idx & 31;
        sqa[h][r] = qp[(long)r * ldq + h0 + h];
        if (dual) sqb[h][r] = qp[(long)r * ldq + 128 + h0 + h];
    }
    #pragma unroll
    for (int i = 0; i < 8; i++) {
        int idx = tid + i * 256;
        int r = idx >> 5, h = idx & 31;
        skb[h][r] = kp[(long)r * ldk + 128 + h0 + h];
        if (dual) ska[h][r] = kp[(long)r * ldk + h0 + h];
    }
    if (tid < 32) sw[tid] = W2[h0 + tid];
    __syncthreads();

    #pragma unroll 4
    for (int h = 0; h < 32; h++) {
        float w = sw[h];
        float2 a1r = *(const float2*)&sqa[h][ty * 2];
        float4 b1r = *(const float4*)&skb[h][tx * 4];
        float a1v[2] = {a1r.x, a1r.y};
        float b1v[4] = {b1r.x, b1r.y, b1r.z, b1r.w};
        #pragma unroll
        for (int i = 0; i < 2; i++)
            #pragma unroll
            for (int j = 0; j < 4; j++)
                acc[i][j] += fmaxf(a1v[i] + b1v[j], 0.f) * w;
        if (dual) {
            float2 qb = *(const float2*)&sqb[h][ty * 2];
            float4 ka = *(const float4*)&ska[h][tx * 4];
            float qv[2] = {qb.x, qb.y};
            float kv[4] = {ka.x, ka.y, ka.z, ka.w};
            #pragma unroll
            for (int i = 0; i < 2; i++)
                #pragma unroll
                for (int j = 0; j < 4; j++)
                    acc[i][j] += fmaxf(kv[j] + qv[i], 0.f) * w;
        }
    }

    float* outp = lg + (long)hq * LGSZ;
    #pragma unroll
    for (int i = 0; i < 2; i++) {
        int q = q0 + ty * 2 + i;
        #pragma unroll
        for (int j = 0; j < 4; j++) {
            int k = k0 + tx * 4 + j;
            outp[((long)b * SEQ + q) * SEQ + k] = acc[i][j];
        }
    }
}

// ---------------- fused softmax + (probs @ VW) + bias + residual + LN ------
// Block: 8 q-rows, 256 threads. Phase 1: per-warp row softmax (unnormalized e
// into smem, 1/sum kept in register). Phase 2: GEMM vs VW, scale, LN.
__global__ void attn_ln_kernel(const float* __restrict__ lg,
                               const float* __restrict__ mask, const float* __restrict__ b2p,
                               const float* __restrict__ VW, int ldvw,
                               const float* __restrict__ bias, const float* __restrict__ res,
                               const float* __restrict__ g, const float* __restrict__ be,
                               float* __restrict__ out, int sym)
{
    __shared__ float sprob[8][264];
    __shared__ float Bs[32][132];
    int m0 = blockIdx.x * 8;
    int b = m0 >> 8;
    int tid = threadIdx.x;
    int w = tid >> 5, lane = tid & 31;
    int q = m0 + w;                      // this warp's global row
    float c2 = 2.f * b2p[0];

    // ---- phase 1: softmax of row q (256 wide) ----
    float xv[8];
    #pragma unroll
    for (int i = 0; i < 8; i++) {
        int k = lane + 32 * i;
        long roff = (long)q * SEQ + k;
        float xx = 0.f;
        #pragma unroll
        for (int p = 0; p < 4; p++) xx += lg[(long)p * LGSZ + roff];
        if (sym) {
            long coff = (long)b * SEQ * SEQ + (long)k * SEQ + (q & 255);
            #pragma unroll
            for (int p = 0; p < 4; p++) xx += lg[(long)p * LGSZ + coff];
        }
        xv[i] = xx + c2 + mask[roff] * (-1e9f);
    }
    float mx = xv[0];
    #pragma unroll
    for (int i = 1; i < 8; i++) mx = fmaxf(mx, xv[i]);
    #pragma unroll
    for (int o = 16; o; o >>= 1) mx = fmaxf(mx, __shfl_xor_sync(0xffffffffu, mx, o));
    float ssum = 0.f;
    #pragma unroll
    for (int i = 0; i < 8; i++) {
        float e = __expf(xv[i] - mx);
        ssum += e;
        sprob[w][lane + 32 * i] = e;
    }
    #pragma unroll
    for (int o = 16; o; o >>= 1) ssum += __shfl_xor_sync(0xffffffffu, ssum, o);
    float inv = 1.f / ssum;
    __syncthreads();

    // ---- phase 2: acc = sum_k sprob[row][k] * VW[b*SEQ+k][:] ----
    int tr = w, tc = lane;
    float acc[4] = {};
    for (int k0 = 0; k0 < 256; k0 += 32) {
        #pragma unroll
        for (int i = 0; i < 4; i++) {
            int idx = tid + i * 256;
            int n4 = idx & 31, kb = idx >> 5;
            *(float4*)&Bs[kb][n4 * 4] =
                *(const float4*)&VW[(long)(b * SEQ + k0 + kb) * ldvw + n4 * 4];
        }
        __syncthreads();
        #pragma unroll
        for (int kk = 0; kk < 32; kk++) {
            float a = sprob[tr][k0 + kk];
            float4 bv = *(const float4*)&Bs[kk][tc * 4];
            acc[0] += a * bv.x; acc[1] += a * bv.y;
            acc[2] += a * bv.z; acc[3] += a * bv.w;
        }
        __syncthreads();
    }

    // ---- epilogue: scale, bias, residual, LayerNorm ----
    float v[4];
    #pragma unroll
    for (int j = 0; j < 4; j++) {
        int n = tc * 4 + j;
        v[j] = acc[j] * inv + bias[n] + res[(long)q * 128 + n];
    }
    float s = v[0] + v[1] + v[2] + v[3];
    #pragma unroll
    for (int o = 16; o; o >>= 1) s += __shfl_xor_sync(0xffffffffu, s, o);
    float mean = s * (1.f / 128.f);
    float vs = 0.f;
    #pragma unroll
    for (int j = 0; j < 4; j++) { float d = v[j] - mean; vs += d * d; }
    #pragma unroll
    for (int o = 16; o; o >>= 1) vs += __shfl_xor_sync(0xffffffffu, vs, o);
    float invstd = rsqrtf(vs * (1.f / 128.f) + 1e-6f);
    #pragma unroll
    for (int j = 0; j < 4; j++) {
        int n = tc * 4 + j;
        out[(long)q * 128 + n] = (v[j] - mean) * invstd * g[n] + be[n];
    }
}

// ---------------- fused GEMM + bias + residual + LayerNorm (FFN tail) ------
__global__ void gemm_ln_kernel(const float* __restrict__ A, int lda,
                               const float* __restrict__ B, int ldb,
                               const float* __restrict__ bias, const float* __restrict__ res,
                               const float* __restrict__ g, const float* __restrict__ be,
                               float* __restrict__ out, int K)
{
    __shared__ float As[32][12];
    __shared__ float Bs[32][132];
    int m0 = blockIdx.x * 8;
    int tid = threadIdx.x;
    int tr = tid >> 5, tc = tid & 31;
    float acc[4] = {};

    for (int k0 = 0; k0 < K; k0 += 32) {
        {
            int k = tid & 31, mm = tid >> 5;
            As[k][mm] = A[(long)(m0 + mm) * lda + k0 + k];
        }
        #pragma unroll
        for (int i = 0; i < 4; i++) {
            int idx = tid + i * 256;
            int n4 = idx & 31, kb = idx >> 5;
            *(float4*)&Bs[kb][n4 * 4] = *(const float4*)&B[(long)(k0 + kb) * ldb + n4 * 4];
        }
        __syncthreads();
        #pragma unroll
        for (int kk = 0; kk < 32; kk++) {
            float a = As[kk][tr];
            float4 b = *(const float4*)&Bs[kk][tc * 4];
            acc[0] += a * b.x; acc[1] += a * b.y;
            acc[2] += a * b.z; acc[3] += a * b.w;
        }
        __syncthreads();
    }

    int r = m0 + tr;
    float v[4];
    #pragma unroll
    for (int j = 0; j < 4; j++) {
        int n = tc * 4 + j;
        v[j] = acc[j] + bias[n] + res[(long)r * 128 + n];
    }
    float s = v[0] + v[1] + v[2] + v[3];
    #pragma unroll
    for (int o = 16; o; o >>= 1) s += __shfl_xor_sync(0xffffffffu, s, o);
    float mean = s * (1.f / 128.f);
    float vs = 0.f;
    #pragma unroll
    for (int j = 0; j < 4; j++) { float d = v[j] - mean; vs += d * d; }
    #pragma unroll
    for (int o = 16; o; o >>= 1) vs += __shfl_xor_sync(0xffffffffu, vs, o);
    float inv = rsqrtf(vs * (1.f / 128.f) + 1e-6f);
    #pragma unroll
    for (int j = 0; j < 4; j++) {
        int n = tc * 4 + j;
        out[(long)r * 128 + n] = (v[j] - mean) * inv * g[n] + be[n];
    }
}

// ---------------- host orchestration ----------------
extern "C" void kernel_launch(void* const* d_in, const int* in_sizes, int n_in,
                              void* d_out, int out_size)
{
    (void)in_sizes; (void)n_in; (void)out_size;
    const float* x    = (const float*)d_in[0];
    const float* enc  = (const float*)d_in[1];
    const float* cmsk = (const float*)d_in[2];
    const float* dmsk = (const float*)d_in[3];
    const float* W1q  = (const float*)d_in[4];
    const float* W1k  = (const float*)d_in[5];
    const float* b1   = (const float*)d_in[6];
    const float* W2   = (const float*)d_in[7];
    const float* b2   = (const float*)d_in[8];
    const float* Ww1  = (const float*)d_in[9];
    const float* bw1  = (const float*)d_in[10];
    const float* Wd1  = (const float*)d_in[11];
    const float* bd1  = (const float*)d_in[12];
    const float* Ww2  = (const float*)d_in[13];
    const float* bw2  = (const float*)d_in[14];
    const float* Wd2  = (const float*)d_in[15];
    const float* bd2  = (const float*)d_in[16];
    const float* Wf1  = (const float*)d_in[17];
    const float* bf1  = (const float*)d_in[18];
    const float* Wf2  = (const float*)d_in[19];
    const float* bf2  = (const float*)d_in[20];
    const float* ln1g = (const float*)d_in[21];
    const float* ln1b = (const float*)d_in[22];
    const float* ln2g = (const float*)d_in[23];
    const float* ln2b = (const float*)d_in[24];
    const float* ln3g = (const float*)d_in[25];
    const float* ln3b = (const float*)d_in[26];
    float* out = (float*)d_out;

    float *Wb1, *Wb2, *bb1, *bb2, *buf1, *buf2, *Tq, *lg, *o1, *o2, *fh;
    cudaGetSymbolAddress((void**)&Wb1,   g_Wbig1);
    cudaGetSymbolAddress((void**)&Wb2,   g_Wbig2);
    cudaGetSymbolAddress((void**)&bb1,   g_bbig1);
    cudaGetSymbolAddress((void**)&bb2,   g_bbig2);
    cudaGetSymbolAddress((void**)&buf1,  g_buf1);
    cudaGetSymbolAddress((void**)&buf2,  g_buf2);
    cudaGetSymbolAddress((void**)&Tq,    g_Tq);
    cudaGetSymbolAddress((void**)&lg,    g_lg);
    cudaGetSymbolAddress((void**)&o1,    g_o1);
    cudaGetSymbolAddress((void**)&o2,    g_o2);
    cudaGetSymbolAddress((void**)&fh,    g_fh);

    dim3 simGrid(SEQ / 64, SEQ / 32, BSZ * 4);   // 512 blocks

    // ---- prep (weights only): Wbig tiles + bias row ----
    prep_kernel<<<dim3(12, 5, 2), 256>>>(Ww1, Ww2, W1q, W1k, Wd1, Wd2,
                                         bw1, bw2, b1, Wb1, Wb2, bb1, bb2);

    // ---- batched projection: buf = [TA | TB | VW] for x and enc ----
    sgemm2x4_kernel<<<dim3(6, 32, 2), 256>>>(x, Wb1, bb1, buf1,
                                             enc, Wb2, bb2, buf2,
                                             128, 128, 384, 384, 0);

    // ---- self-attention: logits = S + S^T (symmetry) ----
    sim_kernel<<<simGrid, 256>>>(buf1, 384, buf1, 384, W2, lg, 0);
    attn_ln_kernel<<<MROWS / 8, 256>>>(lg, cmsk, b2, buf1 + 256, 384,
                                       bd1, x, ln1g, ln1b, o1, 1);

    // ---- cross-attention ----
    sgemm2x4_kernel<<<dim3(4, 32, 1), 256>>>(o1, Wb2, bb2, Tq,
                                             0, 0, 0, 0,
                                             128, 128, 384, 256, 0);
    sim_kernel<<<simGrid, 256>>>(Tq, 256, buf2, 384, W2, lg, 1);
    attn_ln_kernel<<<MROWS / 8, 256>>>(lg, dmsk, b2, buf2 + 256, 384,
                                       bd2, o1, ln2g, ln2b, o2, 0);

    // ---- FFN ----
    sgemm2x4_kernel<<<dim3(8, 32, 1), 256>>>(o2, Wf1, bf1, fh, 0, 0, 0, 0,
                                             128, 128, 512, 512, 1);
    gemm_ln_kernel<<<MROWS / 8, 256>>>(fh, 512, Wf2, 128,
                                       bf2, o2, ln3g, ln3b, out, 512);
}

// round 9
// speedup vs baseline: 1.2032x; 1.0807x over previous
#include <cuda_runtime.h>

#define BSZ 4
#define SEQ 256
#define DIM 128
#define HID 128
#define DFF 512
#define MROWS (BSZ*SEQ)   // 1024
#define LGSZ (BSZ*SEQ*SEQ)

// ---------------- scratch (device globals; no allocations) ----------------
__device__ float g_Wbig1[DIM*384];    // [Ww1@W1q | Ww1@W1k | Ww1@Wd1]
__device__ float g_Wbig2[DIM*384];
__device__ float g_bbig1[384];        // [bw1@W1q+b1 | bw1@W1k | bw1@Wd1]
__device__ float g_bbig2[384];
__device__ float g_buf1[MROWS*384];   // [T1A | T1B | VW1]
__device__ float g_buf2[MROWS*384];   // [TkA | TkB | VW2]
__device__ float g_Tq  [MROWS*256];   // [TqA | TqB]
__device__ float g_lg  [4*LGSZ];      // sim partials (4 H-quarters)
__device__ float g_lgT [4*LGSZ];      // transposed partials (self-attn only)
__device__ float g_o1 [MROWS*DIM];
__device__ float g_o2 [MROWS*DIM];
__device__ float g_fh [MROWS*DFF];

// ---------------- prep: Wbig tiles (y<4) + bbig (y==4), both sets (z) ------
__global__ void prep_kernel(const float* __restrict__ Ww1, const float* __restrict__ Ww2,
                            const float* __restrict__ W1q, const float* __restrict__ W1k,
                            const float* __restrict__ Wd1, const float* __restrict__ Wd2,
                            const float* __restrict__ bw1, const float* __restrict__ bw2,
                            const float* __restrict__ b1,
                            float* __restrict__ Wbig1, float* __restrict__ Wbig2,
                            float* __restrict__ bbig1, float* __restrict__ bbig2)
{
    const float* Ww = blockIdx.z ? Ww2 : Ww1;
    const float* Wd = blockIdx.z ? Wd2 : Wd1;
    const float* bw = blockIdx.z ? bw2 : bw1;
    float* Wbig = blockIdx.z ? Wbig2 : Wbig1;
    float* bbig = blockIdx.z ? bbig2 : bbig1;
    int n0p = blockIdx.x * 32;             // 0..352
    int grp = n0p >> 7;                    // 0:W1q 1:W1k 2:Wd
    const float* Bsrc = ((grp == 0) ? W1q : (grp == 1) ? W1k : Wd) + (n0p & 127);
    int tid = threadIdx.x;

    if (blockIdx.y == 4) {                 // bias row: bbig[n0p .. n0p+32)
        int w = tid >> 5, lane = tid & 31;
        for (int c = w; c < 32; c += 8) {
            int np = n0p + c;
            float s = 0.f;
            #pragma unroll
            for (int i = 0; i < 4; i++) {
                int k = lane + 32 * i;
                s += bw[k] * Bsrc[k * 128 + c];
            }
            #pragma unroll
            for (int o = 16; o; o >>= 1) s += __shfl_xor_sync(0xffffffffu, s, o);
            if (lane == 0) {
                if (grp == 0) s += b1[np & 127];
                bbig[np] = s;
            }
        }
        return;
    }

    int m0 = blockIdx.y * 32;
    __shared__ float As[32][34], Bs[32][34];
    int tx = tid & 15, ty = tid >> 4;
    float a00 = 0.f, a01 = 0.f, a10 = 0.f, a11 = 0.f;
    for (int k0 = 0; k0 < 128; k0 += 32) {
        #pragma unroll
        for (int i = 0; i < 4; i++) {
            int idx = tid + i * 256;
            int ka = idx & 31, ma = idx >> 5;
            As[ka][ma] = Ww[(m0 + ma) * 128 + k0 + ka];
            int nb = idx & 31, kb = idx >> 5;
            Bs[kb][nb] = Bsrc[(k0 + kb) * 128 + nb];
        }
        __syncthreads();
        #pragma unroll
        for (int kk = 0; kk < 32; kk++) {
            float2 a = *(const float2*)&As[kk][ty * 2];
            float2 b = *(const float2*)&Bs[kk][tx * 2];
            a00 += a.x * b.x; a01 += a.x * b.y;
            a10 += a.y * b.x; a11 += a.y * b.y;
        }
        __syncthreads();
    }
    int m = m0 + ty * 2, n = n0p + tx * 2;
    Wbig[m * 384 + n]           = a00;
    Wbig[m * 384 + n + 1]       = a01;
    Wbig[(m + 1) * 384 + n]     = a10;
    Wbig[(m + 1) * 384 + n + 1] = a11;
}

// ---------------- SGEMM 32x64 tile, 256 thr, 2x4 micro ---------------------
__global__ void sgemm2x4_kernel(const float* __restrict__ A0, const float* __restrict__ B0,
                                const float* __restrict__ bias0, float* __restrict__ C0,
                                const float* __restrict__ A1, const float* __restrict__ B1,
                                const float* __restrict__ bias1, float* __restrict__ C1,
                                int K, int lda, int ldb, int ldc, int relu)
{
    __shared__ float As[32][34];
    __shared__ float Bs[32][68];
    int z = blockIdx.z;
    bool use1 = (z == 1) && (C1 != 0);
    const float* A = use1 ? A1 : A0;
    const float* B = use1 ? B1 : B0;
    const float* bias = use1 ? bias1 : bias0;
    float* C = use1 ? C1 : C0;
    int m0 = blockIdx.y * 32, n0 = blockIdx.x * 64;
    int tid = threadIdx.x;
    int tx = tid & 15, ty = tid >> 4;
    float acc[2][4] = {};

    for (int k0 = 0; k0 < K; k0 += 32) {
        #pragma unroll
        for (int i = 0; i < 4; i++) {
            int idx = tid + i * 256;
            int ka = idx & 31, ma = idx >> 5;
            As[ka][ma] = A[(long)(m0 + ma) * lda + k0 + ka];
        }
        #pragma unroll
        for (int i = 0; i < 8; i++) {
            int idx = tid + i * 256;
            int nb = idx & 63, kb = idx >> 6;
            Bs[kb][nb] = B[(long)(k0 + kb) * ldb + n0 + nb];
        }
        __syncthreads();
        #pragma unroll
        for (int kk = 0; kk < 32; kk++) {
            float2 a = *(const float2*)&As[kk][ty * 2];
            float4 b = *(const float4*)&Bs[kk][tx * 4];
            float bv[4] = {b.x, b.y, b.z, b.w};
            #pragma unroll
            for (int j = 0; j < 4; j++) {
                acc[0][j] += a.x * bv[j];
                acc[1][j] += a.y * bv[j];
            }
        }
        __syncthreads();
    }
    int m = m0 + ty * 2, n = n0 + tx * 4;
    float bb[4] = {0.f, 0.f, 0.f, 0.f};
    if (bias) {
        #pragma unroll
        for (int j = 0; j < 4; j++) bb[j] = bias[n + j];
    }
    #pragma unroll
    for (int i = 0; i < 2; i++) {
        float4 o4;
        float v0 = acc[i][0] + bb[0], v1 = acc[i][1] + bb[1];
        float v2 = acc[i][2] + bb[2], v3 = acc[i][3] + bb[3];
        if (relu) { v0=fmaxf(v0,0.f); v1=fmaxf(v1,0.f); v2=fmaxf(v2,0.f); v3=fmaxf(v3,0.f); }
        o4.x=v0; o4.y=v1; o4.z=v2; o4.w=v3;
        *(float4*)&C[(long)(m + i) * ldc + n] = o4;
    }
}

// ---------------- pairwise similarity -------------------------------------
// dual=0 (self): term1 only; ALSO writes transposed tile into lgT (coalesced)
// dual=1 (cross): both terms, lg only.
__global__ void sim_kernel(const float* __restrict__ qbase, int ldq,
                           const float* __restrict__ kbase, int ldk,
                           const float* __restrict__ W2,
                           float* __restrict__ lg, float* __restrict__ lgT, int dual)
{
    __shared__ float sqa[32][34];
    __shared__ float sqb[32][34];
    __shared__ float skb[32][68];
    __shared__ float ska[32][68];
    __shared__ float sw[32];

    int z = blockIdx.z, b = z >> 2, hq = z & 3;
    int h0 = hq * 32;
    int q0 = blockIdx.y * 32, k0 = blockIdx.x * 64;
    const float* qp = qbase + (long)(b * SEQ + q0) * ldq;
    const float* kp = kbase + (long)(b * SEQ + k0) * ldk;
    int tid = threadIdx.x;
    int tx = tid & 15, ty = tid >> 4;
    float acc[2][4] = {};

    #pragma unroll
    for (int i = 0; i < 4; i++) {
        int idx = tid + i * 256;
        int r = idx >> 5, h = idx & 31;
        sqa[h][r] = qp[(long)r * ldq + h0 + h];
        if (dual) sqb[h][r] = qp[(long)r * ldq + 128 + h0 + h];
    }
    #pragma unroll
    for (int i = 0; i < 8; i++) {
        int idx = tid + i * 256;
        int r = idx >> 5, h = idx & 31;
        skb[h][r] = kp[(long)r * ldk + 128 + h0 + h];
        if (dual) ska[h][r] = kp[(long)r * ldk + h0 + h];
    }
    if (tid < 32) sw[tid] = W2[h0 + tid];
    __syncthreads();

    #pragma unroll 4
    for (int h = 0; h < 32; h++) {
        float w = sw[h];
        float2 a1r = *(const float2*)&sqa[h][ty * 2];
        float4 b1r = *(const float4*)&skb[h][tx * 4];
        float a1v[2] = {a1r.x, a1r.y};
        float b1v[4] = {b1r.x, b1r.y, b1r.z, b1r.w};
        #pragma unroll
        for (int i = 0; i < 2; i++)
            #pragma unroll
            for (int j = 0; j < 4; j++)
                acc[i][j] += fmaxf(a1v[i] + b1v[j], 0.f) * w;
        if (dual) {
            float2 qb = *(const float2*)&sqb[h][ty * 2];
            float4 ka = *(const float4*)&ska[h][tx * 4];
            float qv[2] = {qb.x, qb.y};
            float kv[4] = {ka.x, ka.y, ka.z, ka.w};
            #pragma unroll
            for (int i = 0; i < 2; i++)
                #pragma unroll
                for (int j = 0; j < 4; j++)
                    acc[i][j] += fmaxf(kv[j] + qv[i], 0.f) * w;
        }
    }

    float* outp = lg + (long)hq * LGSZ;
    #pragma unroll
    for (int i = 0; i < 2; i++) {
        int q = q0 + ty * 2 + i;
        #pragma unroll
        for (int j = 0; j < 4; j++) {
            int k = k0 + tx * 4 + j;
            outp[((long)b * SEQ + q) * SEQ + k] = acc[i][j];
        }
    }

    if (!dual) {
        // transpose tile through smem (reuse skb: 32*68=2176 >= 64*33=2112)
        __syncthreads();
        float* st = &skb[0][0];
        #pragma unroll
        for (int i = 0; i < 2; i++) {
            int ql = ty * 2 + i;
            #pragma unroll
            for (int j = 0; j < 4; j++) {
                int kl = tx * 4 + j;
                st[kl * 33 + ql] = acc[i][j];
            }
        }
        __syncthreads();
        float* outT = lgT + (long)hq * LGSZ;
        #pragma unroll
        for (int i = 0; i < 8; i++) {
            int idx = tid + i * 256;       // 0..2047
            int r = idx >> 5, c = idx & 31;
            outT[((long)b * SEQ + k0 + r) * SEQ + q0 + c] = st[r * 33 + c];
        }
    }
}

// ---------------- fused softmax + (probs @ VW) + bias + residual + LN ------
// Block: 8 q-rows, 256 threads. sym path reads lgT (coalesced) instead of
// transposed lg. Phase-2 VW chunks are register-prefetched (double buffer).
__global__ void attn_ln_kernel(const float* __restrict__ lg, const float* __restrict__ lgT,
                               const float* __restrict__ mask, const float* __restrict__ b2p,
                               const float* __restrict__ VW, int ldvw,
                               const float* __restrict__ bias, const float* __restrict__ res,
                               const float* __restrict__ g, const float* __restrict__ be,
                               float* __restrict__ out, int sym)
{
    __shared__ float sprob[8][264];
    __shared__ float Bs[32][132];
    int m0 = blockIdx.x * 8;
    int b = m0 >> 8;
    int tid = threadIdx.x;
    int w = tid >> 5, lane = tid & 31;
    int q = m0 + w;
    float c2 = 2.f * b2p[0];

    // ---- phase 1: softmax of row q (all reads row-coalesced) ----
    float xv[8];
    #pragma unroll
    for (int i = 0; i < 8; i++) {
        int k = lane + 32 * i;
        long roff = (long)q * SEQ + k;
        float xx = 0.f;
        #pragma unroll
        for (int p = 0; p < 4; p++) xx += lg[(long)p * LGSZ + roff];
        if (sym) {
            #pragma unroll
            for (int p = 0; p < 4; p++) xx += lgT[(long)p * LGSZ + roff];
        }
        xv[i] = xx + c2 + mask[roff] * (-1e9f);
    }
    float mx = xv[0];
    #pragma unroll
    for (int i = 1; i < 8; i++) mx = fmaxf(mx, xv[i]);
    #pragma unroll
    for (int o = 16; o; o >>= 1) mx = fmaxf(mx, __shfl_xor_sync(0xffffffffu, mx, o));
    float ssum = 0.f;
    #pragma unroll
    for (int i = 0; i < 8; i++) {
        float e = __expf(xv[i] - mx);
        ssum += e;
        sprob[w][lane + 32 * i] = e;
    }
    #pragma unroll
    for (int o = 16; o; o >>= 1) ssum += __shfl_xor_sync(0xffffffffu, ssum, o);
    float inv = 1.f / ssum;

    // ---- phase 2: acc = sum_k sprob[row][k] * VW[b*SEQ+k][:] (dbl-buffered)
    int tr = w, tc = lane;
    float acc[4] = {};
    float4 rv[4];
    #pragma unroll
    for (int i = 0; i < 4; i++) {
        int idx = tid + i * 256;
        int n4 = idx & 31, kb = idx >> 5;
        rv[i] = *(const float4*)&VW[(long)(b * SEQ + kb) * ldvw + n4 * 4];
    }
    __syncthreads();      // sprob ready
    for (int k0 = 0; ; k0 += 32) {
        #pragma unroll
        for (int i = 0; i < 4; i++) {
            int idx = tid + i * 256;
            int n4 = idx & 31, kb = idx >> 5;
            *(float4*)&Bs[kb][n4 * 4] = rv[i];
        }
        __syncthreads();
        bool more = (k0 + 32 < 256);
        if (more) {
            #pragma unroll
            for (int i = 0; i < 4; i++) {
                int idx = tid + i * 256;
                int n4 = idx & 31, kb = idx >> 5;
                rv[i] = *(const float4*)&VW[(long)(b * SEQ + k0 + 32 + kb) * ldvw + n4 * 4];
            }
        }
        #pragma unroll
        for (int kk = 0; kk < 32; kk++) {
            float a = sprob[tr][k0 + kk];
            float4 bv = *(const float4*)&Bs[kk][tc * 4];
            acc[0] += a * bv.x; acc[1] += a * bv.y;
            acc[2] += a * bv.z; acc[3] += a * bv.w;
        }
        if (!more) break;
        __syncthreads();
    }

    // ---- epilogue: scale, bias, residual, LayerNorm ----
    float v[4];
    #pragma unroll
    for (int j = 0; j < 4; j++) {
        int n = tc * 4 + j;
        v[j] = acc[j] * inv + bias[n] + res[(long)q * 128 + n];
    }
    float s = v[0] + v[1] + v[2] + v[3];
    #pragma unroll
    for (int o = 16; o; o >>= 1) s += __shfl_xor_sync(0xffffffffu, s, o);
    float mean = s * (1.f / 128.f);
    float vs = 0.f;
    #pragma unroll
    for (int j = 0; j < 4; j++) { float d = v[j] - mean; vs += d * d; }
    #pragma unroll
    for (int o = 16; o; o >>= 1) vs += __shfl_xor_sync(0xffffffffu, vs, o);
    float invstd = rsqrtf(vs * (1.f / 128.f) + 1e-6f);
    #pragma unroll
    for (int j = 0; j < 4; j++) {
        int n = tc * 4 + j;
        out[(long)q * 128 + n] = (v[j] - mean) * invstd * g[n] + be[n];
    }
}

// ---------------- fused GEMM + bias + residual + LayerNorm (FFN tail) ------
__global__ void gemm_ln_kernel(const float* __restrict__ A, int lda,
                               const float* __restrict__ B, int ldb,
                               const float* __restrict__ bias, const float* __restrict__ res,
                               const float* __restrict__ g, const float* __restrict__ be,
                               float* __restrict__ out, int K)
{
    __shared__ float As[32][12];
    __shared__ float Bs[32][132];
    int m0 = blockIdx.x * 8;
    int tid = threadIdx.x;
    int tr = tid >> 5, tc = tid & 31;
    float acc[4] = {};

    for (int k0 = 0; k0 < K; k0 += 32) {
        {
            int k = tid & 31, mm = tid >> 5;
            As[k][mm] = A[(long)(m0 + mm) * lda + k0 + k];
        }
        #pragma unroll
        for (int i = 0; i < 4; i++) {
            int idx = tid + i * 256;
            int n4 = idx & 31, kb = idx >> 5;
            *(float4*)&Bs[kb][n4 * 4] = *(const float4*)&B[(long)(k0 + kb) * ldb + n4 * 4];
        }
        __syncthreads();
        #pragma unroll
        for (int kk = 0; kk < 32; kk++) {
            float a = As[kk][tr];
            float4 b = *(const float4*)&Bs[kk][tc * 4];
            acc[0] += a * b.x; acc[1] += a * b.y;
            acc[2] += a * b.z; acc[3] += a * b.w;
        }
        __syncthreads();
    }

    int r = m0 + tr;
    float v[4];
    #pragma unroll
    for (int j = 0; j < 4; j++) {
        int n = tc * 4 + j;
        v[j] = acc[j] + bias[n] + res[(long)r * 128 + n];
    }
    float s = v[0] + v[1] + v[2] + v[3];
    #pragma unroll
    for (int o = 16; o; o >>= 1) s += __shfl_xor_sync(0xffffffffu, s, o);
    float mean = s * (1.f / 128.f);
    float vs = 0.f;
    #pragma unroll
    for (int j = 0; j < 4; j++) { float d = v[j] - mean; vs += d * d; }
    #pragma unroll
    for (int o = 16; o; o >>= 1) vs += __shfl_xor_sync(0xffffffffu, vs, o);
    float inv = rsqrtf(vs * (1.f / 128.f) + 1e-6f);
    #pragma unroll
    for (int j = 0; j < 4; j++) {
        int n = tc * 4 + j;
        out[(long)r * 128 + n] = (v[j] - mean) * inv * g[n] + be[n];
    }
}

// ---------------- host orchestration ----------------
extern "C" void kernel_launch(void* const* d_in, const int* in_sizes, int n_in,
                              void* d_out, int out_size)
{
    (void)in_sizes; (void)n_in; (void)out_size;
    const float* x    = (const float*)d_in[0];
    const float* enc  = (const float*)d_in[1];
    const float* cmsk = (const float*)d_in[2];
    const float* dmsk = (const float*)d_in[3];
    const float* W1q  = (const float*)d_in[4];
    const float* W1k  = (const float*)d_in[5];
    const float* b1   = (const float*)d_in[6];
    const float* W2   = (const float*)d_in[7];
    const float* b2   = (const float*)d_in[8];
    const float* Ww1  = (const float*)d_in[9];
    const float* bw1  = (const float*)d_in[10];
    const float* Wd1  = (const float*)d_in[11];
    const float* bd1  = (const float*)d_in[12];
    const float* Ww2  = (const float*)d_in[13];
    const float* bw2  = (const float*)d_in[14];
    const float* Wd2  = (const float*)d_in[15];
    const float* bd2  = (const float*)d_in[16];
    const float* Wf1  = (const float*)d_in[17];
    const float* bf1  = (const float*)d_in[18];
    const float* Wf2  = (const float*)d_in[19];
    const float* bf2  = (const float*)d_in[20];
    const float* ln1g = (const float*)d_in[21];
    const float* ln1b = (const float*)d_in[22];
    const float* ln2g = (const float*)d_in[23];
    const float* ln2b = (const float*)d_in[24];
    const float* ln3g = (const float*)d_in[25];
    const float* ln3b = (const float*)d_in[26];
    float* out = (float*)d_out;

    float *Wb1, *Wb2, *bb1, *bb2, *buf1, *buf2, *Tq, *lg, *lgT, *o1, *o2, *fh;
    cudaGetSymbolAddress((void**)&Wb1,   g_Wbig1);
    cudaGetSymbolAddress((void**)&Wb2,   g_Wbig2);
    cudaGetSymbolAddress((void**)&bb1,   g_bbig1);
    cudaGetSymbolAddress((void**)&bb2,   g_bbig2);
    cudaGetSymbolAddress((void**)&buf1,  g_buf1);
    cudaGetSymbolAddress((void**)&buf2,  g_buf2);
    cudaGetSymbolAddress((void**)&Tq,    g_Tq);
    cudaGetSymbolAddress((void**)&lg,    g_lg);
    cudaGetSymbolAddress((void**)&lgT,   g_lgT);
    cudaGetSymbolAddress((void**)&o1,    g_o1);
    cudaGetSymbolAddress((void**)&o2,    g_o2);
    cudaGetSymbolAddress((void**)&fh,    g_fh);

    dim3 simGrid(SEQ / 64, SEQ / 32, BSZ * 4);   // 512 blocks

    // ---- prep (weights only): Wbig tiles + bias row ----
    prep_kernel<<<dim3(12, 5, 2), 256>>>(Ww1, Ww2, W1q, W1k, Wd1, Wd2,
                                         bw1, bw2, b1, Wb1, Wb2, bb1, bb2);

    // ---- batched projection: buf = [TA | TB | VW] for x and enc ----
    sgemm2x4_kernel<<<dim3(6, 32, 2), 256>>>(x, Wb1, bb1, buf1,
                                             enc, Wb2, bb2, buf2,
                                             128, 128, 384, 384, 0);

    // ---- self-attention: logits = S + S^T (lgT written coalesced by sim) --
    sim_kernel<<<simGrid, 256>>>(buf1, 384, buf1, 384, W2, lg, lgT, 0);
    attn_ln_kernel<<<MROWS / 8, 256>>>(lg, lgT, cmsk, b2, buf1 + 256, 384,
                                       bd1, x, ln1g, ln1b, o1, 1);

    // ---- cross-attention ----
    sgemm2x4_kernel<<<dim3(4, 32, 1), 256>>>(o1, Wb2, bb2, Tq,
                                             0, 0, 0, 0,
                                             128, 128, 384, 256, 0);
    sim_kernel<<<simGrid, 256>>>(Tq, 256, buf2, 384, W2, lg, lgT, 1);
    attn_ln_kernel<<<MROWS / 8, 256>>>(lg, lgT, dmsk, b2, buf2 + 256, 384,
                                       bd2, o1, ln2g, ln2b, o2, 0);

    // ---- FFN ----
    sgemm2x4_kernel<<<dim3(8, 32, 1), 256>>>(o2, Wf1, bf1, fh, 0, 0, 0, 0,
                                             128, 128, 512, 512, 1);
    gemm_ln_kernel<<<MROWS / 8, 256>>>(fh, 512, Wf2, 128,
                                       bf2, o2, ln3g, ln3b, out, 512);
}